// round 11
// baseline (speedup 1.0000x reference)
#include <cuda_runtime.h>

// Fixed shapes from reference setup_inputs
#define TT 4
#define BB 32
#define CC 256
#define HW 1024               // 32x32 plane
#define TB 128                // TT*BB
#define NSTAT 131072.0        // TB*HW
#define EPSV 1e-5
#define TSTRIDE (BB*CC*HW)    // element stride between timesteps

typedef unsigned long long ull;

// Per-channel stat accumulators (double) + packed spike bits (4 MB).
// g_spk layout (producer K3 / consumer K4):
//   word = plane*32 + cg*4 + k   (plane=(t*BB+b)*CC+c, cg=col>>2, k=row>>3)
//   bit  = (row&7)*4 + j         (j = col&3)
__device__ double g_sum1[CC], g_sumsq1[CC], g_sum2[CC], g_sumsq2[CC];
__device__ unsigned g_spk[(TT * BB * CC * HW) / 32];

// ---- packed f32x2 helpers (sm_103a FFMA2 path; ptxas won't auto-fuse) ----
__device__ __forceinline__ ull pk(float lo, float hi) {
    ull r;
    asm("mov.b64 %0, {%1, %2};" : "=l"(r)
        : "r"(__float_as_uint(lo)), "r"(__float_as_uint(hi)));
    return r;
}
__device__ __forceinline__ void upk(float& lo, float& hi, ull p) {
    unsigned a, b;
    asm("mov.b64 {%0, %1}, %2;" : "=r"(a), "=r"(b) : "l"(p));
    lo = __uint_as_float(a); hi = __uint_as_float(b);
}
__device__ __forceinline__ ull fma2(ull a, ull b, ull c) {
    ull d; asm("fma.rn.f32x2 %0, %1, %2, %3;" : "=l"(d) : "l"(a), "l"(b), "l"(c));
    return d;
}
__device__ __forceinline__ ull add2(ull a, ull b) {
    ull d; asm("add.rn.f32x2 %0, %1, %2;" : "=l"(d) : "l"(a), "l"(b));
    return d;
}
__device__ __forceinline__ ull mul2(ull a, ull b) {
    ull d; asm("mul.rn.f32x2 %0, %1, %2;" : "=l"(d) : "l"(a), "l"(b));
    return d;
}

// ---------------------------------------------------------------------------
// K1: depthwise 3x3 conv + bias, per-channel sum/sumsq (BN1 stats).
// Warp = 4 planes; lane&7 = column group (float4). Packed f32x2 math.
// ---------------------------------------------------------------------------
__global__ void __launch_bounds__(256) k_conv_stats(
    const float* __restrict__ x, const float* __restrict__ cw,
    const float* __restrict__ cb)
{
    const int lane = threadIdx.x & 31, warp = threadIdx.x >> 5;
    const int cg = lane & 7;
    const int plane = blockIdx.x * 32 + warp * 4 + (lane >> 3);
    const int c = plane & (CC - 1);
    const float* xp = x + (size_t)plane * HW + cg * 4;

    if (blockIdx.x == 0) {  // zero BN2 stats (K1 never reads them)
        g_sum2[threadIdx.x] = 0.0; g_sumsq2[threadIdx.x] = 0.0;
    }

    ull wp[9];
    #pragma unroll
    for (int i = 0; i < 9; i++) { float wv = __ldg(&cw[c * 9 + i]); wp[i] = pk(wv, wv); }
    const float bias = __ldg(&cb[c]);
    const ull biasp = pk(bias, bias);

    ull acc0a = 0, acc0b = 0, acc1a = 0, acc1b = 0, sp = 0, ssp = 0;

    #pragma unroll 8
    for (int r = 0; r < 32; r++) {
        const float4 v = __ldg(reinterpret_cast<const float4*>(xp + r * 32));
        float hl = __shfl_up_sync(0xffffffffu, v.w, 1);   if (cg == 0) hl = 0.f;
        float hr = __shfl_down_sync(0xffffffffu, v.x, 1); if (cg == 7) hr = 0.f;
        const ull v01 = pk(v.x, v.y), v23 = pk(v.z, v.w);
        const ull p0 = pk(hl, v.x), p2 = pk(v.y, v.z), p4 = pk(v.w, hr);
        ull a01 = fma2(wp[0], p0, fma2(wp[1], v01, mul2(wp[2], p2)));
        ull a23 = fma2(wp[0], p2, fma2(wp[1], v23, mul2(wp[2], p4)));
        ull m01 = fma2(wp[3], p0, fma2(wp[4], v01, mul2(wp[5], p2)));
        ull m23 = fma2(wp[3], p2, fma2(wp[4], v23, mul2(wp[5], p4)));
        ull d01 = fma2(wp[6], p0, fma2(wp[7], v01, mul2(wp[8], p2)));
        ull d23 = fma2(wp[6], p2, fma2(wp[7], v23, mul2(wp[8], p4)));
        if (r) {  // output row r-1 complete
            ull y01 = add2(add2(acc0a, d01), biasp);
            ull y23 = add2(add2(acc0b, d23), biasp);
            sp  = add2(sp, add2(y01, y23));
            ssp = fma2(y01, y01, ssp);
            ssp = fma2(y23, y23, ssp);
        }
        acc0a = add2(acc1a, m01); acc0b = add2(acc1b, m23);
        acc1a = a01; acc1b = a23;
    }
    {   // output row 31 (bottom halo = 0)
        ull y01 = add2(acc0a, biasp);
        ull y23 = add2(acc0b, biasp);
        sp  = add2(sp, add2(y01, y23));
        ssp = fma2(y01, y01, ssp);
        ssp = fma2(y23, y23, ssp);
    }
    float sl, sh_, ql, qh;
    upk(sl, sh_, sp); upk(ql, qh, ssp);
    float s = sl + sh_, ss = ql + qh;
    #pragma unroll
    for (int o = 4; o > 0; o >>= 1) {  // reduce within 8-lane plane group
        s  += __shfl_xor_sync(0xffffffffu, s, o);
        ss += __shfl_xor_sync(0xffffffffu, ss, o);
    }
    if (cg == 0) {
        atomicAdd(&g_sum1[c], (double)s);
        atomicAdd(&g_sumsq1[c], (double)ss);
    }
}

// ---------------------------------------------------------------------------
// K3: fused conv+LIF (R8 structure: warp = 4 planes, 1-row prefetch) with
// packed f32x2 math. 0.5*scale1 folded into weights, 0.5*shift1 into shift_h:
//   h = 0.5*vm + (conv' + shift_h)
// ---------------------------------------------------------------------------
__global__ void __launch_bounds__(128) k_lif(
    const float* __restrict__ x, const float* __restrict__ cw,
    const float* __restrict__ cb, const float* __restrict__ g1,
    const float* __restrict__ b1)
{
    const int lane = threadIdx.x & 31, warp = threadIdx.x >> 5;
    const int cg = lane & 7;
    const int plane = blockIdx.x * 16 + warp * 4 + (lane >> 3); // b*CC + c
    const int c = plane & (CC - 1);
    const float* xp = x + (size_t)plane * HW + cg * 4;

    const double mu  = g_sum1[c] * (1.0 / NSTAT);
    const double var = g_sumsq1[c] * (1.0 / NSTAT) - mu * mu;
    const float scale1 = __ldg(&g1[c]) * (float)rsqrt(var + EPSV);
    const float shift_h = 0.5f * (__ldg(&b1[c]) + (__ldg(&cb[c]) - (float)mu) * scale1);
    const float ws = 0.5f * scale1;
    const ull shp = pk(shift_h, shift_h);
    const ull halfp = pk(0.5f, 0.5f);
    ull wp[9];
    #pragma unroll
    for (int i = 0; i < 9; i++) {
        float wv = __ldg(&cw[c * 9 + i]) * ws;
        wp[i] = pk(wv, wv);
    }

    ull acc0a[TT], acc0b[TT], acc1a[TT], acc1b[TT], vp01[TT], vp23[TT];
    float4 vbuf[TT];
    unsigned spw[TT];
    #pragma unroll
    for (int t = 0; t < TT; t++) {
        acc0a[t] = 0; acc0b[t] = 0; acc1a[t] = 0; acc1b[t] = 0;
        vp01[t] = 0; vp23[t] = 0; spw[t] = 0u;
        vbuf[t] = __ldg(reinterpret_cast<const float4*>(
                        xp + (size_t)t * TSTRIDE));   // preload row 0
    }
    float s2 = 0.f, ss2 = 0.f;
    ull s2p = 0, ss2p = 0;

    #pragma unroll 2
    for (int r = 0; r < 32; r++) {
        // ---- prefetch row r+1 first (row 31 reloads itself: L1 hit) ----
        float4 vnext[TT];
        const int rn = (r < 31) ? r + 1 : 31;
        #pragma unroll
        for (int t = 0; t < TT; t++)
            vnext[t] = __ldg(reinterpret_cast<const float4*>(
                             xp + (size_t)t * TSTRIDE + rn * 32));

        const bool out_valid = (r >= 1);
        const int sh = ((r - 1) & 7) * 4;
        ull vm01 = 0, vm23 = 0;              // membrane, chains over t
        #pragma unroll
        for (int t = 0; t < TT; t++) {
            const float4 v = vbuf[t];
            float hl = __shfl_up_sync(0xffffffffu, v.w, 1);   if (cg == 0) hl = 0.f;
            float hr = __shfl_down_sync(0xffffffffu, v.x, 1); if (cg == 7) hr = 0.f;
            const ull v01 = pk(v.x, v.y), v23 = pk(v.z, v.w);
            const ull p0 = pk(hl, v.x), p2 = pk(v.y, v.z), p4 = pk(v.w, hr);
            ull a01 = fma2(wp[0], p0, fma2(wp[1], v01, mul2(wp[2], p2)));
            ull a23 = fma2(wp[0], p2, fma2(wp[1], v23, mul2(wp[2], p4)));
            ull m01 = fma2(wp[3], p0, fma2(wp[4], v01, mul2(wp[5], p2)));
            ull m23 = fma2(wp[3], p2, fma2(wp[4], v23, mul2(wp[5], p4)));
            ull d01 = fma2(wp[6], p0, fma2(wp[7], v01, mul2(wp[8], p2)));
            ull d23 = fma2(wp[6], p2, fma2(wp[7], v23, mul2(wp[8], p4)));
            if (out_valid) {   // output row r-1 for timestep t
                ull h01 = fma2(vm01, halfp, add2(add2(acc0a[t], d01), shp));
                ull h23 = fma2(vm23, halfp, add2(add2(acc0b[t], d23), shp));
                float hx, hy, hz, hw;
                upk(hx, hy, h01); upk(hz, hw, h23);
                bool f0 = hx >= 1.f, f1 = hy >= 1.f, f2 = hz >= 1.f, f3 = hw >= 1.f;
                vm01 = pk(f0 ? 0.f : hx, f1 ? 0.f : hy);
                vm23 = pk(f2 ? 0.f : hz, f3 ? 0.f : hw);
                unsigned nib = (f0 ? 1u : 0u) | (f1 ? 2u : 0u)
                             | (f2 ? 4u : 0u) | (f3 ? 8u : 0u);
                spw[t] |= nib << sh;
                ull z01 = add2(pk(f0 ? 1.f : 0.f, f1 ? 1.f : 0.f), vp01[t]);
                ull z23 = add2(pk(f2 ? 1.f : 0.f, f3 ? 1.f : 0.f), vp23[t]);
                s2p  = add2(s2p, add2(z01, z23));
                ss2p = fma2(z01, z01, ss2p);
                ss2p = fma2(z23, z23, ss2p);
            }
            acc0a[t] = add2(acc1a[t], m01); acc0b[t] = add2(acc1b[t], m23);
            acc1a[t] = a01; acc1b[t] = a23;
            vp01[t] = v01; vp23[t] = v23;
            vbuf[t] = vnext[t];
        }
        if (out_valid && (((r - 1) & 7) == 7)) {  // flush rows (r-1 = 7,15,23)
            const int k = (r - 1) >> 3;
            #pragma unroll
            for (int t = 0; t < TT; t++) {
                g_spk[((size_t)(t * BB * CC) + plane) * 32 + cg * 4 + k] = spw[t];
                spw[t] = 0u;
            }
        }
    }
    {   // output row 31 (conv' = acc0; bottom halo = 0); vp = x row 31
        ull vm01 = 0, vm23 = 0;
        #pragma unroll
        for (int t = 0; t < TT; t++) {
            ull h01 = fma2(vm01, halfp, add2(acc0a[t], shp));
            ull h23 = fma2(vm23, halfp, add2(acc0b[t], shp));
            float hx, hy, hz, hw;
            upk(hx, hy, h01); upk(hz, hw, h23);
            bool f0 = hx >= 1.f, f1 = hy >= 1.f, f2 = hz >= 1.f, f3 = hw >= 1.f;
            vm01 = pk(f0 ? 0.f : hx, f1 ? 0.f : hy);
            vm23 = pk(f2 ? 0.f : hz, f3 ? 0.f : hw);
            unsigned nib = (f0 ? 1u : 0u) | (f1 ? 2u : 0u)
                         | (f2 ? 4u : 0u) | (f3 ? 8u : 0u);
            spw[t] |= nib << 28;  // (31&7)*4
            ull z01 = add2(pk(f0 ? 1.f : 0.f, f1 ? 1.f : 0.f), vp01[t]);
            ull z23 = add2(pk(f2 ? 1.f : 0.f, f3 ? 1.f : 0.f), vp23[t]);
            s2p  = add2(s2p, add2(z01, z23));
            ss2p = fma2(z01, z01, ss2p);
            ss2p = fma2(z23, z23, ss2p);
            g_spk[((size_t)(t * BB * CC) + plane) * 32 + cg * 4 + 3] = spw[t];
        }
    }
    {
        float al, ah, bl, bh;
        upk(al, ah, s2p); upk(bl, bh, ss2p);
        s2 = al + ah; ss2 = bl + bh;
    }
    #pragma unroll
    for (int o = 4; o > 0; o >>= 1) {  // reduce within 8-lane plane group
        s2  += __shfl_xor_sync(0xffffffffu, s2, o);
        ss2 += __shfl_xor_sync(0xffffffffu, ss2, o);
    }
    if (cg == 0) {
        atomicAdd(&g_sum2[c], (double)s2);
        atomicAdd(&g_sumsq2[c], (double)ss2);
    }
}

// ---------------------------------------------------------------------------
// K4: out = BN2(spike + x). One block = one (t,b,c) plane; params once/block.
// Block 0 zeros BN1 stats for the next launch.
// ---------------------------------------------------------------------------
__global__ void __launch_bounds__(256) k_bn2(
    const float* __restrict__ x, const float* __restrict__ g2,
    const float* __restrict__ b2, float* __restrict__ out)
{
    __shared__ float s_scale, s_shift;
    const int c = blockIdx.x & (CC - 1);

    if (threadIdx.x == 0) {
        double m   = g_sum2[c] * (1.0 / NSTAT);
        double var = g_sumsq2[c] * (1.0 / NSTAT) - m * m;
        float  sc  = __ldg(&g2[c]) * (float)rsqrt(var + EPSV);
        s_scale = sc;
        s_shift = __ldg(&b2[c]) - (float)m * sc;
    }
    if (blockIdx.x == 0) {  // reset BN1 stats for next launch
        g_sum1[threadIdx.x] = 0.0; g_sumsq1[threadIdx.x] = 0.0;
    }
    __syncthreads();
    const float scale2 = s_scale, shift2 = s_shift;

    const unsigned i4 = blockIdx.x * 256u + threadIdx.x;  // float4 index
    const float4 xv = reinterpret_cast<const float4*>(x)[i4];

    // word = plane*32 + cg*4 + k ; plane=i4>>8, cg=i4&7, k=(i4>>6)&3
    const unsigned widx = (i4 >> 8) * 32u + (i4 & 7u) * 4u + ((i4 >> 6) & 3u);
    const unsigned wbits = g_spk[widx];
    const int sh = (int)((i4 >> 1) & 0x1Cu);  // ((row&7)*4)

    float4 o;
    o.x = (xv.x + (float)((wbits >> (sh + 0)) & 1u)) * scale2 + shift2;
    o.y = (xv.y + (float)((wbits >> (sh + 1)) & 1u)) * scale2 + shift2;
    o.z = (xv.z + (float)((wbits >> (sh + 2)) & 1u)) * scale2 + shift2;
    o.w = (xv.w + (float)((wbits >> (sh + 3)) & 1u)) * scale2 + shift2;
    reinterpret_cast<float4*>(out)[i4] = o;
}

// ---------------------------------------------------------------------------
extern "C" void kernel_launch(void* const* d_in, const int* in_sizes, int n_in,
                              void* d_out, int out_size) {
    const float* x  = (const float*)d_in[0];
    const float* cw = (const float*)d_in[1];
    const float* cb = (const float*)d_in[2];
    const float* g1 = (const float*)d_in[3];
    const float* b1 = (const float*)d_in[4];
    const float* g2 = (const float*)d_in[5];
    const float* b2 = (const float*)d_in[6];
    float* out = (float*)d_out;

    k_conv_stats<<<(TB * CC) / 32, 256>>>(x, cw, cb);    // 1024 blocks
    k_lif<<<(BB * CC) / 16, 128>>>(x, cw, cb, g1, b1);   // 512 blocks
    k_bn2<<<TB * CC, 256>>>(x, g2, b2, out);             // 32768 blocks
}

// round 12
// speedup vs baseline: 1.1449x; 1.1449x over previous
#include <cuda_runtime.h>

// Fixed shapes from reference setup_inputs
#define TT 4
#define BB 32
#define CC 256
#define HW 1024               // 32x32 plane
#define TB 128                // TT*BB
#define NSTAT 131072.0        // TB*HW
#define EPSV 1e-5
#define TSTRIDE (BB*CC*HW)    // element stride between timesteps

// Per-channel stat accumulators (double) + packed spike bits (4 MB).
// g_spk layout (producer K3 / consumer K4):
//   word = plane*32 + cg*4 + k   (plane=(t*BB+b)*CC+c, cg=col>>2, k=row>>3)
//   bit  = (row&7)*4 + j         (j = col&3)
__device__ double g_sum1[CC], g_sumsq1[CC], g_sum2[CC], g_sumsq2[CC];
__device__ unsigned g_spk[(TT * BB * CC * HW) / 32];

// Horizontal 3-tap conv on a float4 strip with scalar edge neighbors.
__device__ __forceinline__ float4 hconv(float w0, float w1, float w2,
                                        float l, float4 v, float r) {
    float4 o;
    o.x = fmaf(w0, l,   fmaf(w1, v.x, w2 * v.y));
    o.y = fmaf(w0, v.x, fmaf(w1, v.y, w2 * v.z));
    o.z = fmaf(w0, v.y, fmaf(w1, v.z, w2 * v.w));
    o.w = fmaf(w0, v.z, fmaf(w1, v.w, w2 * r));
    return o;
}

// ---------------------------------------------------------------------------
// K1: depthwise 3x3 conv + bias, per-channel sum/sumsq (BN1 stats).
// Warp = 4 planes, ASCENDING plane order (leaves the tail of x hot in L2 for
// K3's descending pass). Known-good ~29 us, at its FMA-pipe floor.
// ---------------------------------------------------------------------------
__global__ void __launch_bounds__(256) k_conv_stats(
    const float* __restrict__ x, const float* __restrict__ cw,
    const float* __restrict__ cb)
{
    const int lane = threadIdx.x & 31, warp = threadIdx.x >> 5;
    const int cg = lane & 7;                        // column group
    const int plane = blockIdx.x * 32 + warp * 4 + (lane >> 3);
    const int c = plane & (CC - 1);
    const float* xp = x + (size_t)plane * HW + cg * 4;

    if (blockIdx.x == 0) {  // zero BN2 stats (K1 never reads them)
        g_sum2[threadIdx.x] = 0.0; g_sumsq2[threadIdx.x] = 0.0;
    }

    float w[9];
    #pragma unroll
    for (int i = 0; i < 9; i++) w[i] = __ldg(&cw[c * 9 + i]);
    const float bias = __ldg(&cb[c]);

    float4 acc0 = {0,0,0,0}, acc1 = {0,0,0,0};
    float s = 0.f, ss = 0.f;

    #pragma unroll 8
    for (int r = 0; r < 32; r++) {
        const float4 v = __ldg(reinterpret_cast<const float4*>(xp + r * 32));
        float hl = __shfl_up_sync(0xffffffffu, v.w, 1);   if (cg == 0) hl = 0.f;
        float hr = __shfl_down_sync(0xffffffffu, v.x, 1); if (cg == 7) hr = 0.f;
        float4 a = hconv(w[0], w[1], w[2], hl, v, hr);
        float4 m = hconv(w[3], w[4], w[5], hl, v, hr);
        float4 d = hconv(w[6], w[7], w[8], hl, v, hr);
        if (r) {  // output row r-1 complete
            float yx = acc0.x + d.x + bias, yy = acc0.y + d.y + bias;
            float yz = acc0.z + d.z + bias, yw = acc0.w + d.w + bias;
            s += (yx + yy) + (yz + yw);
            ss = fmaf(yx, yx, fmaf(yy, yy, fmaf(yz, yz, fmaf(yw, yw, ss))));
        }
        acc0.x = acc1.x + m.x; acc0.y = acc1.y + m.y;
        acc0.z = acc1.z + m.z; acc0.w = acc1.w + m.w;
        acc1 = a;
    }
    {   // output row 31 (bottom halo = 0)
        float yx = acc0.x + bias, yy = acc0.y + bias;
        float yz = acc0.z + bias, yw = acc0.w + bias;
        s += (yx + yy) + (yz + yw);
        ss = fmaf(yx, yx, fmaf(yy, yy, fmaf(yz, yz, fmaf(yw, yw, ss))));
    }
    #pragma unroll
    for (int o = 4; o > 0; o >>= 1) {  // reduce within 8-lane plane group
        s  += __shfl_xor_sync(0xffffffffu, s, o);
        ss += __shfl_xor_sync(0xffffffffu, ss, o);
    }
    if (cg == 0) {
        atomicAdd(&g_sum1[c], (double)s);
        atomicAdd(&g_sumsq1[c], (double)ss);
    }
}

// ---------------------------------------------------------------------------
// K3: fused conv+LIF, warp = 4 planes, 1-row prefetch (R8 structure), but
// processed in DESCENDING plane order: K1 just finished reading x ascending,
// so ~126 MB of x's tail is L2-resident — descending turns K3's DRAM reads
// into L2 hits (234 vs 577 cyc), shrinking exposed memory stalls.
// ---------------------------------------------------------------------------
__global__ void __launch_bounds__(128) k_lif(
    const float* __restrict__ x, const float* __restrict__ cw,
    const float* __restrict__ cb, const float* __restrict__ g1,
    const float* __restrict__ b1)
{
    const int lane = threadIdx.x & 31, warp = threadIdx.x >> 5;
    const int cg = lane & 7;
    const int rbid = (int)gridDim.x - 1 - (int)blockIdx.x;      // reversed
    const int plane = rbid * 16 + warp * 4 + (lane >> 3);       // b*CC + c
    const int c = plane & (CC - 1);
    const float* xp = x + (size_t)plane * HW + cg * 4;

    float w[9];
    #pragma unroll
    for (int i = 0; i < 9; i++) w[i] = __ldg(&cw[c * 9 + i]);

    const double mu  = g_sum1[c] * (1.0 / NSTAT);
    const double var = g_sumsq1[c] * (1.0 / NSTAT) - mu * mu;
    const float scale1 = __ldg(&g1[c]) * (float)rsqrt(var + EPSV);
    const float shift1 = __ldg(&b1[c]) + (__ldg(&cb[c]) - (float)mu) * scale1;

    float4 acc0[TT], acc1[TT], vprev[TT], vbuf[TT];
    unsigned spw[TT];
    #pragma unroll
    for (int t = 0; t < TT; t++) {
        acc0[t] = make_float4(0,0,0,0); acc1[t] = make_float4(0,0,0,0);
        vprev[t] = make_float4(0,0,0,0); spw[t] = 0u;
        vbuf[t] = __ldg(reinterpret_cast<const float4*>(
                        xp + (size_t)t * TSTRIDE));   // preload row 0
    }
    float s2 = 0.f, ss2 = 0.f;

    #pragma unroll 2
    for (int r = 0; r < 32; r++) {
        // ---- prefetch row r+1 first (row 31 reloads itself: L1 hit) ----
        float4 vnext[TT];
        const int rn = (r < 31) ? r + 1 : 31;
        #pragma unroll
        for (int t = 0; t < TT; t++)
            vnext[t] = __ldg(reinterpret_cast<const float4*>(
                             xp + (size_t)t * TSTRIDE + rn * 32));

        const bool out_valid = (r >= 1);
        const int sh = ((r - 1) & 7) * 4;        // nibble shift for output row
        float4 vm = make_float4(0,0,0,0);        // membrane, chains over t
        #pragma unroll
        for (int t = 0; t < TT; t++) {
            const float4 v = vbuf[t];
            float hl = __shfl_up_sync(0xffffffffu, v.w, 1);   if (cg == 0) hl = 0.f;
            float hr = __shfl_down_sync(0xffffffffu, v.x, 1); if (cg == 7) hr = 0.f;
            float4 a = hconv(w[0], w[1], w[2], hl, v, hr);
            float4 m = hconv(w[3], w[4], w[5], hl, v, hr);
            float4 d = hconv(w[6], w[7], w[8], hl, v, hr);
            if (out_valid) {   // output row r-1 for timestep t
                float yx = fmaf(acc0[t].x + d.x, scale1, shift1);
                float yy = fmaf(acc0[t].y + d.y, scale1, shift1);
                float yz = fmaf(acc0[t].z + d.z, scale1, shift1);
                float yw = fmaf(acc0[t].w + d.w, scale1, shift1);
                float hx = fmaf(yx - vm.x, 0.5f, vm.x);
                float hy = fmaf(yy - vm.y, 0.5f, vm.y);
                float hz = fmaf(yz - vm.z, 0.5f, vm.z);
                float hw = fmaf(yw - vm.w, 0.5f, vm.w);
                bool f0 = hx >= 1.f, f1 = hy >= 1.f, f2 = hz >= 1.f, f3 = hw >= 1.f;
                vm.x = f0 ? 0.f : hx; vm.y = f1 ? 0.f : hy;
                vm.z = f2 ? 0.f : hz; vm.w = f3 ? 0.f : hw;
                unsigned nib = (f0 ? 1u : 0u) | (f1 ? 2u : 0u)
                             | (f2 ? 4u : 0u) | (f3 ? 8u : 0u);
                spw[t] |= nib << sh;
                float zx = (f0 ? 1.f : 0.f) + vprev[t].x;
                float zy = (f1 ? 1.f : 0.f) + vprev[t].y;
                float zz = (f2 ? 1.f : 0.f) + vprev[t].z;
                float zw = (f3 ? 1.f : 0.f) + vprev[t].w;
                s2 += (zx + zy) + (zz + zw);
                ss2 = fmaf(zx, zx, fmaf(zy, zy, fmaf(zz, zz, fmaf(zw, zw, ss2))));
            }
            acc0[t].x = acc1[t].x + m.x; acc0[t].y = acc1[t].y + m.y;
            acc0[t].z = acc1[t].z + m.z; acc0[t].w = acc1[t].w + m.w;
            acc1[t] = a;
            vprev[t] = v;
            vbuf[t] = vnext[t];
        }
        if (out_valid && (((r - 1) & 7) == 7)) {  // flush rows (r-1 = 7,15,23)
            const int k = (r - 1) >> 3;
            #pragma unroll
            for (int t = 0; t < TT; t++) {
                g_spk[((size_t)(t * BB * CC) + plane) * 32 + cg * 4 + k] = spw[t];
                spw[t] = 0u;
            }
        }
    }
    {   // output row 31 (conv = acc0; bottom halo = 0); vprev = x row 31
        float4 vm = make_float4(0,0,0,0);
        #pragma unroll
        for (int t = 0; t < TT; t++) {
            float yx = fmaf(acc0[t].x, scale1, shift1);
            float yy = fmaf(acc0[t].y, scale1, shift1);
            float yz = fmaf(acc0[t].z, scale1, shift1);
            float yw = fmaf(acc0[t].w, scale1, shift1);
            float hx = fmaf(yx - vm.x, 0.5f, vm.x);
            float hy = fmaf(yy - vm.y, 0.5f, vm.y);
            float hz = fmaf(yz - vm.z, 0.5f, vm.z);
            float hw = fmaf(yw - vm.w, 0.5f, vm.w);
            bool f0 = hx >= 1.f, f1 = hy >= 1.f, f2 = hz >= 1.f, f3 = hw >= 1.f;
            vm.x = f0 ? 0.f : hx; vm.y = f1 ? 0.f : hy;
            vm.z = f2 ? 0.f : hz; vm.w = f3 ? 0.f : hw;
            unsigned nib = (f0 ? 1u : 0u) | (f1 ? 2u : 0u)
                         | (f2 ? 4u : 0u) | (f3 ? 8u : 0u);
            spw[t] |= nib << 28;  // (31&7)*4
            float zx = (f0 ? 1.f : 0.f) + vprev[t].x;
            float zy = (f1 ? 1.f : 0.f) + vprev[t].y;
            float zz = (f2 ? 1.f : 0.f) + vprev[t].z;
            float zw = (f3 ? 1.f : 0.f) + vprev[t].w;
            s2 += (zx + zy) + (zz + zw);
            ss2 = fmaf(zx, zx, fmaf(zy, zy, fmaf(zz, zz, fmaf(zw, zw, ss2))));
            g_spk[((size_t)(t * BB * CC) + plane) * 32 + cg * 4 + 3] = spw[t];
        }
    }
    #pragma unroll
    for (int o = 4; o > 0; o >>= 1) {  // reduce within 8-lane plane group
        s2  += __shfl_xor_sync(0xffffffffu, s2, o);
        ss2 += __shfl_xor_sync(0xffffffffu, ss2, o);
    }
    if (cg == 0) {
        atomicAdd(&g_sum2[c], (double)s2);
        atomicAdd(&g_sumsq2[c], (double)ss2);
    }
}

// ---------------------------------------------------------------------------
// K4: out = BN2(spike + x), ascending order (picks up K3-descending's L2 tail).
// One block = one (t,b,c) plane; params once/block. Block 0 zeros BN1 stats.
// ---------------------------------------------------------------------------
__global__ void __launch_bounds__(256) k_bn2(
    const float* __restrict__ x, const float* __restrict__ g2,
    const float* __restrict__ b2, float* __restrict__ out)
{
    __shared__ float s_scale, s_shift;
    const int c = blockIdx.x & (CC - 1);

    if (threadIdx.x == 0) {
        double m   = g_sum2[c] * (1.0 / NSTAT);
        double var = g_sumsq2[c] * (1.0 / NSTAT) - m * m;
        float  sc  = __ldg(&g2[c]) * (float)rsqrt(var + EPSV);
        s_scale = sc;
        s_shift = __ldg(&b2[c]) - (float)m * sc;
    }
    if (blockIdx.x == 0) {  // reset BN1 stats for next launch
        g_sum1[threadIdx.x] = 0.0; g_sumsq1[threadIdx.x] = 0.0;
    }
    __syncthreads();
    const float scale2 = s_scale, shift2 = s_shift;

    const unsigned i4 = blockIdx.x * 256u + threadIdx.x;  // float4 index
    const float4 xv = reinterpret_cast<const float4*>(x)[i4];

    // word = plane*32 + cg*4 + k ; plane=i4>>8, cg=i4&7, k=(i4>>6)&3
    const unsigned widx = (i4 >> 8) * 32u + (i4 & 7u) * 4u + ((i4 >> 6) & 3u);
    const unsigned wbits = g_spk[widx];
    const int sh = (int)((i4 >> 1) & 0x1Cu);  // ((row&7)*4)

    float4 o;
    o.x = (xv.x + (float)((wbits >> (sh + 0)) & 1u)) * scale2 + shift2;
    o.y = (xv.y + (float)((wbits >> (sh + 1)) & 1u)) * scale2 + shift2;
    o.z = (xv.z + (float)((wbits >> (sh + 2)) & 1u)) * scale2 + shift2;
    o.w = (xv.w + (float)((wbits >> (sh + 3)) & 1u)) * scale2 + shift2;
    reinterpret_cast<float4*>(out)[i4] = o;
}

// ---------------------------------------------------------------------------
extern "C" void kernel_launch(void* const* d_in, const int* in_sizes, int n_in,
                              void* d_out, int out_size) {
    const float* x  = (const float*)d_in[0];
    const float* cw = (const float*)d_in[1];
    const float* cb = (const float*)d_in[2];
    const float* g1 = (const float*)d_in[3];
    const float* b1 = (const float*)d_in[4];
    const float* g2 = (const float*)d_in[5];
    const float* b2 = (const float*)d_in[6];
    float* out = (float*)d_out;

    k_conv_stats<<<(TB * CC) / 32, 256>>>(x, cw, cb);    // 1024 blocks, asc
    k_lif<<<(BB * CC) / 16, 128>>>(x, cw, cb, g1, b1);   // 512 blocks, DESC
    k_bn2<<<TB * CC, 256>>>(x, g2, b2, out);             // 32768 blocks, asc
}